// round 1
// baseline (speedup 1.0000x reference)
#include <cuda_runtime.h>
#include <cuda_bf16.h>

// Problem constants
#define NS   12      // num states (channels)
#define PC   48      // perception channels
#define HID  96      // hidden features
#define HH   512
#define WW   512
#define HW   (HH*WW)     // 262144
#define CHW  (NS*HW)

// Tile config: 32 (w) x 8 (h) pixels per 256-thread block
#define TW 32
#define TH 8
#define TILE_W (TW + 2)   // 34
#define TILE_H (TH + 2)   // 10
#define TILE_CH (TILE_W * TILE_H)  // 340

// Shared memory layout (floats)
#define OFF_TILE 0
#define SZ_TILE  (NS * TILE_CH)          // 4080
#define OFF_PW   (OFF_TILE + SZ_TILE)    // 4080
#define SZ_PW    (NS * 9 * PC)           // 5184  layout [ci*9+tap][co]
#define OFF_PB   (OFF_PW + SZ_PW)        // 9264
#define SZ_PB    PC                      // 48
#define OFF_W1   (OFF_PB + SZ_PB)        // 9312
#define SZ_W1    (HID * PC)              // 4608  layout [f][c]
#define OFF_B1   (OFF_W1 + SZ_W1)        // 13920
#define SZ_B1    HID                     // 96
#define OFF_W2   (OFF_B1 + SZ_B1)        // 14016
#define SZ_W2    (HID * NS)              // 1152  layout [f][o] (transposed)
#define SMEM_FLOATS (OFF_W2 + SZ_W2)     // 15168 floats = 60672 bytes

__global__ __launch_bounds__(256)
void ca_step_kernel(const float* __restrict__ x,
                    const float* __restrict__ pw,
                    const float* __restrict__ pb,
                    const float* __restrict__ w1,
                    const float* __restrict__ b1,
                    const float* __restrict__ w2,
                    const int*   __restrict__ mask,
                    float* __restrict__ out)
{
    extern __shared__ float sm[];
    float* tile = sm + OFF_TILE;
    float* pw_s = sm + OFF_PW;
    float* pb_s = sm + OFF_PB;
    float* w1_s = sm + OFF_W1;
    float* b1_s = sm + OFF_B1;
    float* w2_s = sm + OFF_W2;

    const int tx  = threadIdx.x;           // 0..31
    const int ty  = threadIdx.y;           // 0..7
    const int tid = ty * TW + tx;           // 0..255
    const int w0  = blockIdx.x * TW;
    const int h0  = blockIdx.y * TH;
    const int n   = blockIdx.z;

    const float* xn = x + (size_t)n * CHW;

    // ---- Stage input tile (12 ch, 10x34 with circular halo) ----
    #pragma unroll 4
    for (int i = tid; i < NS * TILE_CH; i += 256) {
        int ci = i / TILE_CH;
        int r  = (i - ci * TILE_CH) / TILE_W;
        int c  = (i - ci * TILE_CH) - r * TILE_W;
        int gh = (h0 + r - 1) & (HH - 1);
        int gw = (w0 + c - 1) & (WW - 1);
        tile[i] = xn[ci * HW + gh * WW + gw];
    }

    // ---- Stage weights ----
    // pw: in [co][ci][kh][kw]  ->  smem [(ci*9+tap)][co]
    for (int i = tid; i < SZ_PW; i += 256) {
        int co  = i % PC;
        int cit = i / PC;            // ci*9 + tap
        pw_s[i] = pw[co * (NS * 9) + cit];
    }
    if (tid < PC)  pb_s[tid] = pb[tid];
    // w1: [f][c] straight copy
    for (int i = tid; i < SZ_W1; i += 256) w1_s[i] = w1[i];
    if (tid < HID) b1_s[tid] = b1[tid];
    // w2: in [o][f] -> smem [f][o]
    for (int i = tid; i < SZ_W2; i += 256) {
        int o = i % NS;
        int f = i / NS;
        w2_s[i] = w2[o * HID + f];
    }

    __syncthreads();

    // ---- Perception: 3x3 conv, 12 -> 48 ----
    float perc[PC];
    #pragma unroll
    for (int i = 0; i < PC; i++) perc[i] = pb_s[i];

    #pragma unroll 1
    for (int ci = 0; ci < NS; ci++) {
        const float* tb = &tile[ci * TILE_CH + ty * TILE_W + tx];
        #pragma unroll
        for (int kh = 0; kh < 3; kh++) {
            #pragma unroll
            for (int kw = 0; kw < 3; kw++) {
                float v = tb[kh * TILE_W + kw];
                const float4* wp =
                    (const float4*)&pw_s[(ci * 9 + kh * 3 + kw) * PC];
                #pragma unroll
                for (int j = 0; j < PC / 4; j++) {
                    float4 w = wp[j];
                    perc[4*j+0] = fmaf(w.x, v, perc[4*j+0]);
                    perc[4*j+1] = fmaf(w.y, v, perc[4*j+1]);
                    perc[4*j+2] = fmaf(w.z, v, perc[4*j+2]);
                    perc[4*j+3] = fmaf(w.w, v, perc[4*j+3]);
                }
            }
        }
    }

    // ---- Per-pixel MLP: 48 -> 96 (ReLU) -> 12, fused ----
    float upd[NS];
    #pragma unroll
    for (int o = 0; o < NS; o++) upd[o] = 0.f;

    #pragma unroll 2
    for (int f = 0; f < HID; f++) {
        const float4* w1p = (const float4*)&w1_s[f * PC];
        float a0 = 0.f, a1 = 0.f, a2 = 0.f, a3 = 0.f;
        #pragma unroll
        for (int j = 0; j < PC / 4; j++) {
            float4 w = w1p[j];
            a0 = fmaf(w.x, perc[4*j+0], a0);
            a1 = fmaf(w.y, perc[4*j+1], a1);
            a2 = fmaf(w.z, perc[4*j+2], a2);
            a3 = fmaf(w.w, perc[4*j+3], a3);
        }
        float hf = (a0 + a1) + (a2 + a3) + b1_s[f];
        hf = fmaxf(hf, 0.f);
        const float4* w2p = (const float4*)&w2_s[f * NS];
        #pragma unroll
        for (int o = 0; o < NS / 4; o++) {
            float4 w = w2p[o];
            upd[4*o+0] = fmaf(w.x, hf, upd[4*o+0]);
            upd[4*o+1] = fmaf(w.y, hf, upd[4*o+1]);
            upd[4*o+2] = fmaf(w.z, hf, upd[4*o+2]);
            upd[4*o+3] = fmaf(w.w, hf, upd[4*o+3]);
        }
    }

    // ---- Masked residual + store ----
    const size_t pix = (size_t)n * CHW + (size_t)(h0 + ty) * WW + (w0 + tx);
    #pragma unroll
    for (int c = 0; c < NS; c++) {
        float xv = tile[c * TILE_CH + (ty + 1) * TILE_W + (tx + 1)];
        int   m  = mask[pix + (size_t)c * HW];
        out[pix + (size_t)c * HW] = xv + (m != 0 ? upd[c] : 0.f);
    }
}

extern "C" void kernel_launch(void* const* d_in, const int* in_sizes, int n_in,
                              void* d_out, int out_size)
{
    const float* x    = (const float*)d_in[0];
    const float* pw   = (const float*)d_in[1];
    const float* pb   = (const float*)d_in[2];
    const float* w1   = (const float*)d_in[3];
    const float* b1   = (const float*)d_in[4];
    const float* w2   = (const float*)d_in[5];
    const int*   mask = (const int*)  d_in[6];
    float* out = (float*)d_out;

    const int smem_bytes = SMEM_FLOATS * sizeof(float);
    static bool attr_set = false;
    if (!attr_set) {
        cudaFuncSetAttribute(ca_step_kernel,
                             cudaFuncAttributeMaxDynamicSharedMemorySize,
                             smem_bytes);
        attr_set = true;
    }

    dim3 block(TW, TH);                 // 256 threads
    dim3 grid(WW / TW, HH / TH, 8);     // 16 x 64 x 8 = 8192 blocks
    ca_step_kernel<<<grid, block, smem_bytes>>>(x, pw, pb, w1, b1, w2, mask, out);
}

// round 2
// speedup vs baseline: 1.5285x; 1.5285x over previous
#include <cuda_runtime.h>
#include <cuda_bf16.h>

// Problem constants
#define NS   12
#define PC   48
#define HID  96
#define HH   512
#define WW   512
#define HW   (HH*WW)
#define CHW  (NS*HW)

// Tile: 32 (w) x 8 (h) pixels per block; 128 threads (32x4), 2 pixels/thread
#define TW 32
#define TH 8
#define TILE_W (TW + 2)                 // 34
#define TILE_H (TH + 2)                 // 10
#define TILE_CH (TILE_W * TILE_H)       // 340

// Shared memory layout (floats), all sub-arrays 16B-aligned
#define OFF_TILE 0
#define SZ_TILE  (NS * TILE_CH)          // 4080
#define OFF_PW   (OFF_TILE + SZ_TILE)    // 4080  (*4 = 16320 B, 16B aligned)
#define SZ_PW    (NS * 9 * PC)           // 5184  layout [ci*9+tap][co]
#define OFF_PB   (OFF_PW + SZ_PW)        // 9264
#define SZ_PB    PC                      // 48
#define OFF_W1   (OFF_PB + SZ_PB)        // 9312
#define SZ_W1    (HID * PC)              // 4608  layout [f][c]
#define OFF_B1   (OFF_W1 + SZ_W1)        // 13920
#define SZ_B1    HID                     // 96
#define OFF_W2   (OFF_B1 + SZ_B1)        // 14016
#define SZ_W2    (HID * NS)              // 1152  layout [f][o]
#define SMEM_FLOATS (OFF_W2 + SZ_W2)     // 15168 floats = 60672 B

typedef unsigned long long u64;

// packed dual-FMA: d.lo = a.lo*b.lo + c.lo ; d.hi = a.hi*b.hi + c.hi
__device__ __forceinline__ u64 fma2(u64 a, u64 b, u64 c) {
    u64 d;
    asm("fma.rn.f32x2 %0, %1, %2, %3;" : "=l"(d) : "l"(a), "l"(b), "l"(c));
    return d;
}
__device__ __forceinline__ u64 pack2(float lo, float hi) {
    u64 d;
    asm("mov.b64 %0, {%1, %2};" : "=l"(d) : "f"(lo), "f"(hi));
    return d;
}
__device__ __forceinline__ float2 unpack2(u64 v) {
    float2 r;
    asm("mov.b64 {%0, %1}, %2;" : "=f"(r.x), "=f"(r.y) : "l"(v));
    return r;
}

__global__ __launch_bounds__(128)
void ca_step_kernel(const float* __restrict__ x,
                    const float* __restrict__ pw,
                    const float* __restrict__ pb,
                    const float* __restrict__ w1,
                    const float* __restrict__ b1,
                    const float* __restrict__ w2,
                    const int*   __restrict__ mask,
                    float* __restrict__ out)
{
    extern __shared__ float sm[];
    float* tile = sm + OFF_TILE;
    float* pw_s = sm + OFF_PW;
    float* pb_s = sm + OFF_PB;
    float* w1_s = sm + OFF_W1;
    float* b1_s = sm + OFF_B1;
    float* w2_s = sm + OFF_W2;

    const int tx  = threadIdx.x;            // 0..31
    const int ty  = threadIdx.y;            // 0..3  (handles rows ty and ty+4)
    const int tid = ty * TW + tx;            // 0..127
    const int w0  = blockIdx.x * TW;
    const int h0  = blockIdx.y * TH;
    const int n   = blockIdx.z;

    const float* xn = x + (size_t)n * CHW;

    // ---- Stage input tile (12 ch, 10x34 with circular halo) ----
    #pragma unroll 4
    for (int i = tid; i < NS * TILE_CH; i += 128) {
        int ci = i / TILE_CH;
        int r  = (i - ci * TILE_CH) / TILE_W;
        int c  = (i - ci * TILE_CH) - r * TILE_W;
        int gh = (h0 + r - 1) & (HH - 1);
        int gw = (w0 + c - 1) & (WW - 1);
        tile[i] = xn[ci * HW + gh * WW + gw];
    }

    // ---- Stage weights ----
    for (int i = tid; i < SZ_PW; i += 128) {        // pw -> [(ci*9+tap)][co]
        int co  = i % PC;
        int cit = i / PC;
        pw_s[i] = pw[co * (NS * 9) + cit];
    }
    if (tid < PC)  pb_s[tid] = pb[tid];
    for (int i = tid; i < SZ_W1; i += 128) w1_s[i] = w1[i];   // [f][c]
    if (tid < HID) b1_s[tid] = b1[tid];
    for (int i = tid; i < SZ_W2; i += 128) {        // w2 -> [f][o]
        int o = i % NS;
        int f = i / NS;
        w2_s[i] = w2[o * HID + f];
    }

    __syncthreads();

    // ---- Perception: 3x3 conv, 12 -> 48, two pixels per thread ----
    // perc*[j] packs channels (2j, 2j+1) as f32x2.
    u64 perc0[PC/2], perc1[PC/2];
    {
        const u64* pbu = (const u64*)pb_s;
        #pragma unroll
        for (int j = 0; j < PC/2; j++) { perc0[j] = pbu[j]; perc1[j] = pbu[j]; }
    }

    #pragma unroll 1
    for (int ci = 0; ci < NS; ci++) {
        const float* tb0 = &tile[ci * TILE_CH + ty * TILE_W + tx];
        const float* tb1 = tb0 + 4 * TILE_W;
        #pragma unroll 1
        for (int kh = 0; kh < 3; kh++) {
            #pragma unroll
            for (int kw = 0; kw < 3; kw++) {
                float v0 = tb0[kh * TILE_W + kw];
                float v1 = tb1[kh * TILE_W + kw];
                u64 vv0 = pack2(v0, v0);
                u64 vv1 = pack2(v1, v1);
                const ulonglong2* wp =
                    (const ulonglong2*)&pw_s[(ci * 9 + kh * 3 + kw) * PC];
                #pragma unroll
                for (int q = 0; q < PC/4; q++) {     // 12 LDS.128
                    ulonglong2 w = wp[q];
                    perc0[2*q+0] = fma2(w.x, vv0, perc0[2*q+0]);
                    perc0[2*q+1] = fma2(w.y, vv0, perc0[2*q+1]);
                    perc1[2*q+0] = fma2(w.x, vv1, perc1[2*q+0]);
                    perc1[2*q+1] = fma2(w.y, vv1, perc1[2*q+1]);
                }
            }
        }
    }

    // ---- Fused per-pixel MLP: 48 -> 96 (ReLU) -> 12, two pixels ----
    u64 upd0[NS/2], upd1[NS/2];
    #pragma unroll
    for (int o = 0; o < NS/2; o++) { upd0[o] = 0ull; upd1[o] = 0ull; }

    #pragma unroll 1
    for (int f = 0; f < HID; f++) {
        const ulonglong2* w1p = (const ulonglong2*)&w1_s[f * PC];
        u64 a00 = 0ull, a01 = 0ull;   // pixel0, 4 scalar chains
        u64 a10 = 0ull, a11 = 0ull;   // pixel1
        #pragma unroll
        for (int q = 0; q < PC/4; q++) {             // 12 LDS.128 shared
            ulonglong2 w = w1p[q];
            a00 = fma2(w.x, perc0[2*q+0], a00);
            a01 = fma2(w.y, perc0[2*q+1], a01);
            a10 = fma2(w.x, perc1[2*q+0], a10);
            a11 = fma2(w.y, perc1[2*q+1], a11);
        }
        float bf = b1_s[f];
        float2 s00 = unpack2(a00), s01 = unpack2(a01);
        float2 s10 = unpack2(a10), s11 = unpack2(a11);
        float h0v = fmaxf((s00.x + s00.y) + (s01.x + s01.y) + bf, 0.f);
        float h1v = fmaxf((s10.x + s10.y) + (s11.x + s11.y) + bf, 0.f);
        u64 hh0 = pack2(h0v, h0v);
        u64 hh1 = pack2(h1v, h1v);
        const ulonglong2* w2p = (const ulonglong2*)&w2_s[f * NS];
        #pragma unroll
        for (int q = 0; q < NS/4; q++) {             // 3 LDS.128 shared
            ulonglong2 w = w2p[q];
            upd0[2*q+0] = fma2(w.x, hh0, upd0[2*q+0]);
            upd0[2*q+1] = fma2(w.y, hh0, upd0[2*q+1]);
            upd1[2*q+0] = fma2(w.x, hh1, upd1[2*q+0]);
            upd1[2*q+1] = fma2(w.y, hh1, upd1[2*q+1]);
        }
    }

    // ---- Masked residual + store (2 pixels x 12 channels) ----
    const size_t pix0 = (size_t)n * CHW + (size_t)(h0 + ty) * WW + (w0 + tx);
    const size_t pix1 = pix0 + (size_t)4 * WW;
    #pragma unroll
    for (int q = 0; q < NS/2; q++) {
        float2 u0 = unpack2(upd0[q]);
        float2 u1 = unpack2(upd1[q]);
        int c0 = 2*q, c1 = 2*q + 1;

        float xv;
        xv = tile[c0 * TILE_CH + (ty + 1) * TILE_W + (tx + 1)];
        out[pix0 + (size_t)c0 * HW] = xv + (mask[pix0 + (size_t)c0 * HW] ? u0.x : 0.f);
        xv = tile[c1 * TILE_CH + (ty + 1) * TILE_W + (tx + 1)];
        out[pix0 + (size_t)c1 * HW] = xv + (mask[pix0 + (size_t)c1 * HW] ? u0.y : 0.f);

        xv = tile[c0 * TILE_CH + (ty + 5) * TILE_W + (tx + 1)];
        out[pix1 + (size_t)c0 * HW] = xv + (mask[pix1 + (size_t)c0 * HW] ? u1.x : 0.f);
        xv = tile[c1 * TILE_CH + (ty + 5) * TILE_W + (tx + 1)];
        out[pix1 + (size_t)c1 * HW] = xv + (mask[pix1 + (size_t)c1 * HW] ? u1.y : 0.f);
    }
}

extern "C" void kernel_launch(void* const* d_in, const int* in_sizes, int n_in,
                              void* d_out, int out_size)
{
    const float* x    = (const float*)d_in[0];
    const float* pw   = (const float*)d_in[1];
    const float* pb   = (const float*)d_in[2];
    const float* w1   = (const float*)d_in[3];
    const float* b1   = (const float*)d_in[4];
    const float* w2   = (const float*)d_in[5];
    const int*   mask = (const int*)  d_in[6];
    float* out = (float*)d_out;

    const int smem_bytes = SMEM_FLOATS * sizeof(float);
    static bool attr_set = false;
    if (!attr_set) {
        cudaFuncSetAttribute(ca_step_kernel,
                             cudaFuncAttributeMaxDynamicSharedMemorySize,
                             smem_bytes);
        attr_set = true;
    }

    dim3 block(TW, 4);                  // 128 threads, 2 pixels each
    dim3 grid(WW / TW, HH / TH, 8);     // 16 x 64 x 8 = 8192 blocks
    ca_step_kernel<<<grid, block, smem_bytes>>>(x, pw, pb, w1, b1, w2, mask, out);
}

// round 4
// speedup vs baseline: 2.4138x; 1.5792x over previous
#include <cuda_runtime.h>
#include <cstdint>

// ---------------- problem constants ----------------
#define NS   12
#define PC   48
#define HID  96
#define HH   512
#define WW   512
#define HW   (HH*WW)
#define CHW  (NS*HW)

#define MT    128         // pixels per tile
#define K1    112         // padded K (108 real) for fused conv+mlp1
#define K1R   108
#define N1    96
#define K2    96
#define N2    16          // 12 padded to 16

// smem strides (floats)
#define SA1   136         // A1/A2 [k][p] stride  (136 mod 32 == 8 -> cf frags)
#define SB1   104         // B1 [k][n] stride     (104 mod 32 == 8 -> cf frags)
#define SB2   24          // B2 [k][n] stride     (24  mod 32 == 8 -> cf frags)
#define SD2   16          // D2 [p][c] stride

// smem layout (byte offsets)
#define SOFF_A1   0
#define SZ_A1     (K1 * SA1 * 4)            // 60928 (A2 = 96*136*4 aliases)
#define SOFF_B1   (SOFF_A1 + SZ_A1)
#define SZ_B1     (K1 * SB1 * 4)            // 46592
#define SOFF_B2   (SOFF_B1 + SZ_B1)
#define SZ_B2     (K2 * SB2 * 4)            // 9216
#define SOFF_D2   (SOFF_B2 + SZ_B2)
#define SZ_D2     (MT * SD2 * 4)            // 8192
#define SOFF_BIAS (SOFF_D2 + SZ_D2)
#define SZ_BIAS   (N1 * 4)
#define SMEM_TOTAL (SOFF_BIAS + SZ_BIAS)    // 125312 B

// ---------------- fused weights (device scratch) ----------------
__device__ float g_B1c[N1 * K1];   // (w1 @ pw), tf32-rounded, k = ci*9+tap, pad 0
__device__ float g_b1c[N1];        // w1 @ pb + b1

__device__ __forceinline__ uint32_t f2tf32(float v) {
    uint32_t t; asm("cvt.rna.tf32.f32 %0, %1;" : "=r"(t) : "f"(v)); return t;
}

__device__ __forceinline__ void mma_tf32(float d[4], const uint32_t a[4],
                                         const uint32_t b[2]) {
    asm volatile(
        "mma.sync.aligned.m16n8k8.row.col.f32.tf32.tf32.f32 "
        "{%0,%1,%2,%3}, {%4,%5,%6,%7}, {%8,%9}, {%0,%1,%2,%3};"
        : "+f"(d[0]), "+f"(d[1]), "+f"(d[2]), "+f"(d[3])
        : "r"(a[0]), "r"(a[1]), "r"(a[2]), "r"(a[3]), "r"(b[0]), "r"(b[1]));
}

// ---------------- setup: fuse conv weights into MLP1 ----------------
__global__ void ca_setup_kernel(const float* __restrict__ pw, const float* __restrict__ pb,
                                const float* __restrict__ w1, const float* __restrict__ b1)
{
    int f = blockIdx.x;        // 0..95
    int k = threadIdx.x;       // 0..127
    if (k < K1) {
        float acc = 0.f;
        if (k < K1R) {
            int ci = k / 9, tap = k % 9;
            #pragma unroll
            for (int c = 0; c < PC; c++)
                acc = fmaf(w1[f * PC + c], pw[(c * NS + ci) * 9 + tap], acc);
        }
        g_B1c[f * K1 + k] = __uint_as_float(f2tf32(acc));
    }
    if (k == 0) {
        float b = b1[f];
        for (int c = 0; c < PC; c++) b = fmaf(w1[f * PC + c], pb[c], b);
        g_b1c[f] = b;
    }
}

// ---------------- main kernel ----------------
__global__ __launch_bounds__(256)
void ca_mma_kernel(const float* __restrict__ x,
                   const float* __restrict__ w2,
                   const int*   __restrict__ mask,
                   float* __restrict__ out)
{
    extern __shared__ __align__(16) float sm[];
    float* A1s   = sm + SOFF_A1 / 4;       // [K1][SA1]  (A2 aliases, [K2][SA1])
    float* B1s   = sm + SOFF_B1 / 4;       // [K1][SB1]
    float* B2s   = sm + SOFF_B2 / 4;       // [K2][SB2]
    float* D2s   = sm + SOFF_D2 / 4;       // [MT][SD2]
    float* biass = sm + SOFF_BIAS / 4;     // [N1]

    const int tid  = threadIdx.x;
    const int wid  = tid >> 5;
    const int lane = tid & 31;
    const int g    = lane >> 2;            // group row
    const int t    = lane & 3;             // thread-in-group
    const int n    = blockIdx.z;
    const int hp   = blockIdx.y;           // rows 2hp, 2hp+1

    // -------- stage constant weights (once per CTA) --------
    for (int i = tid; i < N1 * K1; i += 256) {         // B1: [f][k] -> [k][n=f]
        int f = i / K1, k = i - f * K1;
        B1s[k * SB1 + f] = g_B1c[i];
    }
    for (int i = tid; i < K2 * N2; i += 256) {         // B2: w2[o][f] -> [k=f][n=o]
        int k = i >> 4, o = i & 15;
        B2s[k * SB2 + o] = (o < NS) ? __uint_as_float(f2tf32(w2[o * HID + k])) : 0.f;
    }
    if (tid < N1) biass[tid] = g_b1c[tid];
    // zero A1 pad rows (k = 108..111); never rewritten (A2 alias ends at row 96)
    for (int i = tid; i < (K1 - K1R) * SA1; i += 256)
        A1s[K1R * SA1 + i] = 0.f;
    __syncthreads();

    // per-thread fragment base offsets
    const int m0 = (wid & 7) * 16;
    // bias regs (per n-tile, 2 cols each)
    float bx[12], by[12];
    #pragma unroll
    for (int nt = 0; nt < 12; nt++) {
        bx[nt] = biass[nt * 8 + 2 * t];
        by[nt] = biass[nt * 8 + 2 * t + 1];
    }

    const float* xn = x + (size_t)n * CHW;
    const int p  = tid & 127;              // pixel within tile
    const int hh = tid >> 7;               // channel-half 0/1 (staging & output)

    for (int it = 0; it < 8; it++) {
        const int h  = 2 * hp + (it >> 2);
        const int w0 = (it & 3) << 7;
        const int gwm = (w0 + p + WW - 1) & (WW - 1);
        const int gw0 = (w0 + p) & (WW - 1);
        const int gwp = (w0 + p + 1) & (WW - 1);

        // -------- stage im2col A1 [k][p] (tf32) --------
        float xcen[6];
        #pragma unroll
        for (int cc = 0; cc < 6; cc++) {
            const int ci = 6 * hh + cc;
            #pragma unroll
            for (int dh = 0; dh < 3; dh++) {
                const int gh = (h + dh - 1) & (HH - 1);
                const float* rp = xn + (size_t)ci * HW + (size_t)gh * WW;
                float v0 = __ldg(rp + gwm);
                float v1 = __ldg(rp + gw0);
                float v2 = __ldg(rp + gwp);
                if (dh == 1) xcen[cc] = v1;
                const int kb = ci * 9 + dh * 3;
                A1s[(kb + 0) * SA1 + p] = __uint_as_float(f2tf32(v0));
                A1s[(kb + 1) * SA1 + p] = __uint_as_float(f2tf32(v1));
                A1s[(kb + 2) * SA1 + p] = __uint_as_float(f2tf32(v2));
            }
        }
        __syncthreads();

        // -------- GEMM1: [128 x 112] x [112 x 96] -> acc[12][4] --------
        float acc[12][4];
        #pragma unroll
        for (int nt = 0; nt < 12; nt++)
            #pragma unroll
            for (int q = 0; q < 4; q++) acc[nt][q] = 0.f;

        #pragma unroll 2
        for (int ks = 0; ks < K1 / 8; ks++) {
            const int k0 = ks * 8;
            uint32_t a[4];
            const uint32_t* qa = (const uint32_t*)&A1s[(k0 + t) * SA1 + m0 + g];
            a[0] = qa[0];
            a[1] = qa[8];
            a[2] = qa[4 * SA1];
            a[3] = qa[4 * SA1 + 8];
            const uint32_t* qb = (const uint32_t*)&B1s[(k0 + t) * SB1 + g];
            #pragma unroll
            for (int nt = 0; nt < 12; nt++) {
                uint32_t b[2];
                b[0] = qb[nt * 8];
                b[1] = qb[nt * 8 + 4 * SB1];
                mma_tf32(acc[nt], a, b);
            }
        }
        __syncthreads();   // all warps done reading A1 before A2 overwrite

        // -------- epilogue 1: bias + relu + tf32 -> A2 [k][p] --------
        #pragma unroll
        for (int nt = 0; nt < 12; nt++) {
            const int c0 = nt * 8 + 2 * t;
            float h00 = fmaxf(acc[nt][0] + bx[nt], 0.f);
            float h01 = fmaxf(acc[nt][1] + by[nt], 0.f);
            float h10 = fmaxf(acc[nt][2] + bx[nt], 0.f);
            float h11 = fmaxf(acc[nt][3] + by[nt], 0.f);
            A1s[(c0    ) * SA1 + m0 + g    ] = __uint_as_float(f2tf32(h00));
            A1s[(c0 + 1) * SA1 + m0 + g    ] = __uint_as_float(f2tf32(h01));
            A1s[(c0    ) * SA1 + m0 + g + 8] = __uint_as_float(f2tf32(h10));
            A1s[(c0 + 1) * SA1 + m0 + g + 8] = __uint_as_float(f2tf32(h11));
        }
        __syncthreads();

        // -------- GEMM2: [128 x 96] x [96 x 16] --------
        float acc2[2][4];
        #pragma unroll
        for (int nt = 0; nt < 2; nt++)
            #pragma unroll
            for (int q = 0; q < 4; q++) acc2[nt][q] = 0.f;

        #pragma unroll 3
        for (int ks = 0; ks < K2 / 8; ks++) {
            const int k0 = ks * 8;
            uint32_t a[4];
            const uint32_t* qa = (const uint32_t*)&A1s[(k0 + t) * SA1 + m0 + g];
            a[0] = qa[0];
            a[1] = qa[8];
            a[2] = qa[4 * SA1];
            a[3] = qa[4 * SA1 + 8];
            const uint32_t* qb = (const uint32_t*)&B2s[(k0 + t) * SB2 + g];
            #pragma unroll
            for (int nt = 0; nt < 2; nt++) {
                uint32_t b[2];
                b[0] = qb[nt * 8];
                b[1] = qb[nt * 8 + 4 * SB2];
                mma_tf32(acc2[nt], a, b);
            }
        }

        // -------- write D2 fragments to smem --------
        #pragma unroll
        for (int nt = 0; nt < 2; nt++) {
            const int c0 = nt * 8 + 2 * t;
            *(float2*)&D2s[(m0 + g    ) * SD2 + c0] = make_float2(acc2[nt][0], acc2[nt][1]);
            *(float2*)&D2s[(m0 + g + 8) * SD2 + c0] = make_float2(acc2[nt][2], acc2[nt][3]);
        }
        __syncthreads();

        // -------- masked residual + coalesced store --------
        {
            const size_t pix = (size_t)n * CHW + (size_t)h * WW + (size_t)(w0 + p);
            #pragma unroll
            for (int cc = 0; cc < 6; cc++) {
                const int c = 6 * hh + cc;
                int m = mask[pix + (size_t)c * HW];
                float u = D2s[p * SD2 + c];
                out[pix + (size_t)c * HW] = xcen[cc] + (m ? u : 0.f);
            }
        }
        // no sync needed: next staging writes A1 only; D2s reads done per-thread
        __syncthreads();
    }
}

// ---------------- launch ----------------
extern "C" void kernel_launch(void* const* d_in, const int* in_sizes, int n_in,
                              void* d_out, int out_size)
{
    const float* x    = (const float*)d_in[0];
    const float* pw   = (const float*)d_in[1];
    const float* pb   = (const float*)d_in[2];
    const float* w1   = (const float*)d_in[3];
    const float* b1   = (const float*)d_in[4];
    const float* w2   = (const float*)d_in[5];
    const int*   mask = (const int*)  d_in[6];
    float* out = (float*)d_out;

    static bool attr_set = false;
    if (!attr_set) {
        cudaFuncSetAttribute(ca_mma_kernel,
                             cudaFuncAttributeMaxDynamicSharedMemorySize,
                             SMEM_TOTAL);
        attr_set = true;
    }

    ca_setup_kernel<<<N1, 128>>>(pw, pb, w1, b1);

    dim3 grid(1, HH / 2, 8);      // 2048 CTAs, 8 tiles (128px) each
    ca_mma_kernel<<<grid, 256, SMEM_TOTAL>>>(x, w2, mask, out);
}

// round 5
// speedup vs baseline: 2.6642x; 1.1038x over previous
#include <cuda_runtime.h>
#include <cstdint>

// ---------------- problem constants ----------------
#define NS   12
#define PC   48
#define HID  96
#define HH   512
#define WW   512
#define HW   (HH*WW)
#define CHW  (NS*HW)

#define MT    64          // pixels per tile
#define K1    112         // padded K (108 real) for fused conv+mlp1
#define K1R   108
#define N1    96
#define K2    96
#define N2    16          // 12 padded to 16

// smem strides (floats)
#define SA1   72          // A1/A2 [k][p] stride  (72 mod 32 == 8 -> cf frag reads)
#define SB1   104         // B1 [k][n] stride     (104 mod 32 == 8)
#define SB2   24          // B2 [k][n] stride     (24  mod 32 == 8)
#define SD2   17          // D2 [p][c] stride     (odd -> cf gather)

// smem layout (byte offsets)
#define SOFF_A1   0
#define SZ_A1     (K1 * SA1 * 4)            // 32256 (A2 aliases rows 0..95)
#define SOFF_B1   (SOFF_A1 + SZ_A1)
#define SZ_B1     (K1 * SB1 * 4)            // 46592
#define SOFF_B2   (SOFF_B1 + SZ_B1)
#define SZ_B2     (K2 * SB2 * 4)            // 9216
#define SOFF_D2   (SOFF_B2 + SZ_B2)
#define SZ_D2     (MT * SD2 * 4)            // 4352
#define SOFF_BIAS (SOFF_D2 + SZ_D2)
#define SZ_BIAS   (N1 * 4)
#define SMEM_TOTAL (SOFF_BIAS + SZ_BIAS)    // 92800 B -> 2 CTAs/SM

// ---------------- fused weights (device scratch) ----------------
__device__ float g_B1c[N1 * K1];   // (w1 @ pw), tf32-rounded, k = ci*9+tap, pad 0
__device__ float g_b1c[N1];        // w1 @ pb + b1

__device__ __forceinline__ uint32_t f2tf32(float v) {
    uint32_t t; asm("cvt.rna.tf32.f32 %0, %1;" : "=r"(t) : "f"(v)); return t;
}

__device__ __forceinline__ void mma_tf32(float d[4], const uint32_t a[4],
                                         const uint32_t b[2]) {
    asm volatile(
        "mma.sync.aligned.m16n8k8.row.col.f32.tf32.tf32.f32 "
        "{%0,%1,%2,%3}, {%4,%5,%6,%7}, {%8,%9}, {%0,%1,%2,%3};"
        : "+f"(d[0]), "+f"(d[1]), "+f"(d[2]), "+f"(d[3])
        : "r"(a[0]), "r"(a[1]), "r"(a[2]), "r"(a[3]), "r"(b[0]), "r"(b[1]));
}

// ---------------- setup: fuse conv weights into MLP1 ----------------
__global__ void ca_setup_kernel(const float* __restrict__ pw, const float* __restrict__ pb,
                                const float* __restrict__ w1, const float* __restrict__ b1)
{
    int f = blockIdx.x;        // 0..95
    int k = threadIdx.x;       // 0..127
    if (k < K1) {
        float acc = 0.f;
        if (k < K1R) {
            int ci = k / 9, tap = k % 9;
            #pragma unroll
            for (int c = 0; c < PC; c++)
                acc = fmaf(w1[f * PC + c], pw[(c * NS + ci) * 9 + tap], acc);
        }
        g_B1c[f * K1 + k] = __uint_as_float(f2tf32(acc));
    }
    if (k == 0) {
        float b = b1[f];
        for (int c = 0; c < PC; c++) b = fmaf(w1[f * PC + c], pb[c], b);
        g_b1c[f] = b;
    }
}

// ---------------- main kernel ----------------
__global__ __launch_bounds__(256, 2)
void ca_mma_kernel(const float* __restrict__ x,
                   const float* __restrict__ w2,
                   const int*   __restrict__ mask,
                   float* __restrict__ out)
{
    extern __shared__ __align__(16) float sm[];
    float* A1s   = sm + SOFF_A1 / 4;       // [K1][SA1]  (A2 aliases rows 0..95)
    float* B1s   = sm + SOFF_B1 / 4;       // [K1][SB1]
    float* B2s   = sm + SOFF_B2 / 4;       // [K2][SB2]
    float* D2s   = sm + SOFF_D2 / 4;       // [MT][SD2]
    float* biass = sm + SOFF_BIAS / 4;     // [N1]

    const int tid  = threadIdx.x;
    const int wid  = tid >> 5;
    const int lane = tid & 31;
    const int g    = lane >> 2;            // 0..7
    const int t    = lane & 3;             // 0..3
    const int par  = wid & 1;              // n-split half: n in [48*par, 48*par+48)
    const int m0   = (wid >> 1) * 16;      // m-tile rows (pixels)
    const int n    = blockIdx.z;
    const int h    = blockIdx.y;           // image row

    // -------- stage constant weights (once per CTA) --------
    for (int i = tid; i < N1 * K1; i += 256) {         // B1: [f][k] -> [k][n=f]
        int f = i / K1, k = i - f * K1;
        B1s[k * SB1 + f] = g_B1c[i];
    }
    for (int i = tid; i < K2 * N2; i += 256) {         // B2: w2[o][f] -> [k=f][n=o]
        int k = i >> 4, o = i & 15;
        B2s[k * SB2 + o] = (o < NS) ? __uint_as_float(f2tf32(w2[o * HID + k])) : 0.f;
    }
    if (tid < N1) biass[tid] = g_b1c[tid];
    // zero A1 pad rows (k = 108..111); never rewritten (A2 alias ends at row 96)
    for (int i = tid; i < (K1 - K1R) * SA1; i += 256)
        A1s[K1R * SA1 + i] = 0.f;
    __syncthreads();

    // bias regs for this warp's 6 n-tiles
    float bx[6], by[6];
    #pragma unroll
    for (int nt = 0; nt < 6; nt++) {
        bx[nt] = biass[par * 48 + nt * 8 + 2 * t];
        by[nt] = biass[par * 48 + nt * 8 + 2 * t + 1];
    }

    const float* xn = x + (size_t)n * CHW;
    const int p  = tid & 63;               // pixel within tile
    const int qh = tid >> 6;               // channel quarter 0..3 (3 ch each)

    for (int it = 0; it < 8; it++) {
        const int w0  = it << 6;
        const int gwm = (w0 + p + WW - 1) & (WW - 1);
        const int gw0 = w0 + p;
        const int gwp = (w0 + p + 1) & (WW - 1);

        // -------- stage im2col A1 [k][p] (tf32): 3 channels per thread ----
        float xcen[3];
        #pragma unroll
        for (int cc = 0; cc < 3; cc++) {
            const int ci = 3 * qh + cc;
            #pragma unroll
            for (int dh = 0; dh < 3; dh++) {
                const int gh = (h + dh - 1) & (HH - 1);
                const float* rp = xn + (size_t)ci * HW + (size_t)gh * WW;
                float v0 = __ldg(rp + gwm);
                float v1 = __ldg(rp + gw0);
                float v2 = __ldg(rp + gwp);
                if (dh == 1) xcen[cc] = v1;
                const int kb = ci * 9 + dh * 3;
                A1s[(kb + 0) * SA1 + p] = __uint_as_float(f2tf32(v0));
                A1s[(kb + 1) * SA1 + p] = __uint_as_float(f2tf32(v1));
                A1s[(kb + 2) * SA1 + p] = __uint_as_float(f2tf32(v2));
            }
        }
        __syncthreads();

        // -------- GEMM1: [64 x 112] x [112 x 48(half)] -> acc[6][4] --------
        float acc[6][4];
        #pragma unroll
        for (int nt = 0; nt < 6; nt++)
            #pragma unroll
            for (int q = 0; q < 4; q++) acc[nt][q] = 0.f;

        #pragma unroll 2
        for (int ks = 0; ks < K1 / 8; ks++) {
            const int k0 = ks * 8;
            uint32_t a[4];
            const uint32_t* qa = (const uint32_t*)&A1s[(k0 + t) * SA1 + m0 + g];
            a[0] = qa[0];
            a[1] = qa[8];
            a[2] = qa[4 * SA1];
            a[3] = qa[4 * SA1 + 8];
            const uint32_t* qb = (const uint32_t*)&B1s[(k0 + t) * SB1 + par * 48 + g];
            #pragma unroll
            for (int nt = 0; nt < 6; nt++) {
                uint32_t b[2];
                b[0] = qb[nt * 8];
                b[1] = qb[nt * 8 + 4 * SB1];
                mma_tf32(acc[nt], a, b);
            }
        }
        __syncthreads();   // all warps done reading A1 before A2 overwrite

        // -------- epilogue 1: bias + relu + tf32 -> A2 [k=n1][p] --------
        #pragma unroll
        for (int nt = 0; nt < 6; nt++) {
            const int c0 = par * 48 + nt * 8 + 2 * t;
            float h00 = fmaxf(acc[nt][0] + bx[nt], 0.f);
            float h01 = fmaxf(acc[nt][1] + by[nt], 0.f);
            float h10 = fmaxf(acc[nt][2] + bx[nt], 0.f);
            float h11 = fmaxf(acc[nt][3] + by[nt], 0.f);
            A1s[(c0    ) * SA1 + m0 + g    ] = __uint_as_float(f2tf32(h00));
            A1s[(c0 + 1) * SA1 + m0 + g    ] = __uint_as_float(f2tf32(h01));
            A1s[(c0    ) * SA1 + m0 + g + 8] = __uint_as_float(f2tf32(h10));
            A1s[(c0 + 1) * SA1 + m0 + g + 8] = __uint_as_float(f2tf32(h11));
        }
        __syncthreads();

        // -------- GEMM2: [64 x 96] x [96 x 8(half)] --------
        float acc2[4];
        #pragma unroll
        for (int q = 0; q < 4; q++) acc2[q] = 0.f;

        #pragma unroll 3
        for (int ks = 0; ks < K2 / 8; ks++) {
            const int k0 = ks * 8;
            uint32_t a[4];
            const uint32_t* qa = (const uint32_t*)&A1s[(k0 + t) * SA1 + m0 + g];
            a[0] = qa[0];
            a[1] = qa[8];
            a[2] = qa[4 * SA1];
            a[3] = qa[4 * SA1 + 8];
            uint32_t b[2];
            const uint32_t* qb = (const uint32_t*)&B2s[(k0 + t) * SB2 + par * 8 + g];
            b[0] = qb[0];
            b[1] = qb[4 * SB2];
            mma_tf32(acc2, a, b);
        }

        // -------- write D2 fragments (scalar, cf reads via SD2=17) --------
        {
            const int c0 = par * 8 + 2 * t;
            D2s[(m0 + g    ) * SD2 + c0    ] = acc2[0];
            D2s[(m0 + g    ) * SD2 + c0 + 1] = acc2[1];
            D2s[(m0 + g + 8) * SD2 + c0    ] = acc2[2];
            D2s[(m0 + g + 8) * SD2 + c0 + 1] = acc2[3];
        }
        __syncthreads();

        // -------- masked residual + coalesced store (3 ch per thread) ----
        {
            const size_t pix = (size_t)n * CHW + (size_t)h * WW + (size_t)(w0 + p);
            #pragma unroll
            for (int cc = 0; cc < 3; cc++) {
                const int c = 3 * qh + cc;
                int m = mask[pix + (size_t)c * HW];
                float u = D2s[p * SD2 + c];
                out[pix + (size_t)c * HW] = xcen[cc] + (m ? u : 0.f);
            }
        }
        __syncthreads();   // D2 reads done; also guards next A1 staging vs GEMM2 reads
    }
}

// ---------------- launch ----------------
extern "C" void kernel_launch(void* const* d_in, const int* in_sizes, int n_in,
                              void* d_out, int out_size)
{
    const float* x    = (const float*)d_in[0];
    const float* pw   = (const float*)d_in[1];
    const float* pb   = (const float*)d_in[2];
    const float* w1   = (const float*)d_in[3];
    const float* b1   = (const float*)d_in[4];
    const float* w2   = (const float*)d_in[5];
    const int*   mask = (const int*)  d_in[6];
    float* out = (float*)d_out;

    static bool attr_set = false;
    if (!attr_set) {
        cudaFuncSetAttribute(ca_mma_kernel,
                             cudaFuncAttributeMaxDynamicSharedMemorySize,
                             SMEM_TOTAL);
        attr_set = true;
    }

    ca_setup_kernel<<<N1, 128>>>(pw, pb, w1, b1);

    dim3 grid(1, HH, 8);          // 4096 CTAs, 8 tiles (64px) each
    ca_mma_kernel<<<grid, 256, SMEM_TOTAL>>>(x, w2, mask, out);
}

// round 6
// speedup vs baseline: 5.1561x; 1.9353x over previous
#include <cuda_runtime.h>
#include <cuda_bf16.h>
#include <cstdint>

// ---------------- problem constants ----------------
#define NS   12
#define PC   48
#define HID  96
#define HH   512
#define WW   512
#define HW   (HH*WW)
#define CHW  (NS*HW)

#define MT    64          // pixels per tile
#define K1    128         // 4 groups x 32 slots (27 real taps each)
#define N1    96
#define K2    96
#define N2    16

// smem layout (bytes). Rows are 256B (16 granules of 16B); granule XOR (row&7).
#define SOFF_A1   0                         // A1/A2: 64 rows x 256B
#define SZ_A1     (64 * 256)                // 16384
#define SOFF_B1   (SOFF_A1 + SZ_A1)         // B1: 96 rows x 256B
#define SZ_B1     (96 * 256)                // 24576
#define SOFF_B2   (SOFF_B1 + SZ_B1)         // B2: 16 rows x 256B
#define SZ_B2     (16 * 256)                // 4096
#define SOFF_D2   (SOFF_B2 + SZ_B2)         // D2: 64 x 17 f32
#define SZ_D2     (64 * 17 * 4)             // 4352
#define SOFF_BIAS (SOFF_D2 + SZ_D2)
#define SZ_BIAS   (N1 * 4)
#define SMEM_TOTAL (SOFF_BIAS + SZ_BIAS)    // 49792 B -> 3 CTAs/SM

// ---------------- fused weights (device scratch) ----------------
__device__ __nv_bfloat16 g_B1c[N1 * K1];  // (w1 @ pw) bf16, k = 32*(ci/3)+(ci%3)*9+tap
__device__ float g_b1c[N1];               // w1 @ pb + b1

// ---------------- asm helpers ----------------
__device__ __forceinline__ uint32_t smem_u32(const void* p) {
    uint32_t a;
    asm("{ .reg .u64 t; cvta.to.shared.u64 t, %1; cvt.u32.u64 %0, t; }" : "=r"(a) : "l"(p));
    return a;
}
__device__ __forceinline__ uint32_t pack_bf16x2(float lo, float hi) {
    uint32_t r;
    asm("cvt.rn.bf16x2.f32 %0, %1, %2;" : "=r"(r) : "f"(hi), "f"(lo));
    return r;
}
__device__ __forceinline__ void ldsm_x4(uint32_t r[4], uint32_t addr) {
    asm volatile("ldmatrix.sync.aligned.m8n8.x4.shared.b16 {%0,%1,%2,%3}, [%4];"
                 : "=r"(r[0]), "=r"(r[1]), "=r"(r[2]), "=r"(r[3]) : "r"(addr));
}
__device__ __forceinline__ void ldsm_x2(uint32_t r[2], uint32_t addr) {
    asm volatile("ldmatrix.sync.aligned.m8n8.x2.shared.b16 {%0,%1}, [%2];"
                 : "=r"(r[0]), "=r"(r[1]) : "r"(addr));
}
__device__ __forceinline__ void mma_bf16(float d[4], const uint32_t a[4],
                                         uint32_t b0, uint32_t b1) {
    asm volatile(
        "mma.sync.aligned.m16n8k16.row.col.f32.bf16.bf16.f32 "
        "{%0,%1,%2,%3}, {%4,%5,%6,%7}, {%8,%9}, {%0,%1,%2,%3};"
        : "+f"(d[0]), "+f"(d[1]), "+f"(d[2]), "+f"(d[3])
        : "r"(a[0]), "r"(a[1]), "r"(a[2]), "r"(a[3]), "r"(b0), "r"(b1));
}

// ---------------- setup: fuse conv weights into MLP1 (bf16) ----------------
__global__ void ca_setup_kernel(const float* __restrict__ pw, const float* __restrict__ pb,
                                const float* __restrict__ w1, const float* __restrict__ b1)
{
    int f = blockIdx.x;        // 0..95
    int k = threadIdx.x;       // 0..127
    int grp = k >> 5, slot = k & 31;
    float acc = 0.f;
    if (slot < 27) {
        int ci = 3 * grp + slot / 9;
        int tap = slot % 9;
        #pragma unroll
        for (int c = 0; c < PC; c++)
            acc = fmaf(w1[f * PC + c], pw[(c * NS + ci) * 9 + tap], acc);
    }
    g_B1c[f * K1 + k] = __float2bfloat16(acc);
    if (k == 0) {
        float b = b1[f];
        for (int c = 0; c < PC; c++) b = fmaf(w1[f * PC + c], pb[c], b);
        g_b1c[f] = b;
    }
}

// ---------------- main kernel ----------------
__global__ __launch_bounds__(256, 3)
void ca_mma_kernel(const float* __restrict__ x,
                   const float* __restrict__ w2,
                   const int*   __restrict__ mask,
                   float* __restrict__ out)
{
    extern __shared__ __align__(256) char smem[];
    const uint32_t su  = smem_u32(smem);
    const uint32_t sbA = su + SOFF_A1;
    const uint32_t sbB1= su + SOFF_B1;
    const uint32_t sbB2= su + SOFF_B2;
    float* D2s   = (float*)(smem + SOFF_D2);    // [64][17]
    float* biass = (float*)(smem + SOFF_BIAS);  // [96]

    const int tid  = threadIdx.x;
    const int wid  = tid >> 5;
    const int lane = tid & 31;
    const int sw   = lane & 7;
    const int par  = wid & 1;              // n-half: [48*par, 48*par+48)
    const int m0   = (wid >> 1) * 16;
    const int n    = blockIdx.z;
    const int h    = blockIdx.y;

    // -------- stage constant weights (once per CTA) --------
    {   // B1: [f][k] bf16, granule-copy with XOR swizzle
        const uint16_t* src = (const uint16_t*)g_B1c;
        for (int i = tid; i < N1 * 16; i += 256) {
            int f = i >> 4, gj = i & 15;
            uint4 q = *(const uint4*)(src + f * K1 + gj * 8);
            *(uint4*)(smem + SOFF_B1 + f * 256 + 16 * (gj ^ (f & 7))) = q;
        }
    }
    for (int i = tid; i < N2 * K2; i += 256) { // B2: w2[o][f] -> [n=o][k=f]
        int o = i / K2, k = i - o * K2;
        __nv_bfloat16 v = (o < NS) ? __float2bfloat16(w2[o * HID + k])
                                   : __float2bfloat16(0.f);
        *(__nv_bfloat16*)(smem + SOFF_B2 + o * 256 + 16 * ((k >> 3) ^ (o & 7)) + 2 * (k & 7)) = v;
    }
    if (tid < N1) biass[tid] = g_b1c[tid];
    __syncthreads();

    // bias regs for this warp's 6 n-tiles
    const int t = lane & 3, g = lane >> 2;
    float bx[6], by[6];
    #pragma unroll
    for (int nt = 0; nt < 6; nt++) {
        bx[nt] = biass[par * 48 + nt * 8 + 2 * t];
        by[nt] = biass[par * 48 + nt * 8 + 2 * t + 1];
    }

    // ldmatrix per-lane address components
    const uint32_t aA_row = sbA + (uint32_t)(m0 + 8 * ((lane >> 3) & 1) + sw) * 256;
    const int akg = lane >> 4;                   // 0/1 : k-granule offset
    const uint32_t bB_row = sbB1 + (uint32_t)(par * 48 + 8 * (lane >> 4) + sw) * 256;
    const int bkg = (lane >> 3) & 1;
    const uint32_t bB2_row = sbB2 + (uint32_t)(par * 8 + sw) * 256;
    const int b2kg = (lane >> 3) & 1;            // lanes 16-31 mirror 0-15

    const float* xn = x + (size_t)n * CHW;
    const int p  = tid & 63;               // pixel within tile
    const int qh = tid >> 6;               // channel group 0..3 (3 ch each)

    for (int it = 0; it < 8; it++) {
        const int w0  = it << 6;
        const int gwm = (w0 + p + WW - 1) & (WW - 1);
        const int gw0 = w0 + p;
        const int gwp = (w0 + p + 1) & (WW - 1);

        // -------- stage im2col A1: 27 taps -> 4 x STS.128, XOR swizzle ----
        float vals[27];
        #pragma unroll
        for (int cc = 0; cc < 3; cc++) {
            const int ci = 3 * qh + cc;
            #pragma unroll
            for (int dh = 0; dh < 3; dh++) {
                const int gh = (h + dh - 1) & (HH - 1);
                const float* rp = xn + (size_t)ci * HW + (size_t)gh * WW;
                vals[cc * 9 + dh * 3 + 0] = __ldg(rp + gwm);
                vals[cc * 9 + dh * 3 + 1] = __ldg(rp + gw0);
                vals[cc * 9 + dh * 3 + 2] = __ldg(rp + gwp);
            }
        }
        float xcen[3] = { vals[4], vals[13], vals[22] };
        #pragma unroll
        for (int j = 0; j < 4; j++) {
            uint32_t q[4];
            #pragma unroll
            for (int wq = 0; wq < 4; wq++) {
                const int s0 = 8 * j + 2 * wq;
                float lo = (s0     < 27) ? vals[s0]     : 0.f;
                float hi = (s0 + 1 < 27) ? vals[s0 + 1] : 0.f;
                q[wq] = pack_bf16x2(lo, hi);
            }
            const int gran = (4 * qh + j) ^ (p & 7);
            *(uint4*)(smem + SOFF_A1 + p * 256 + gran * 16) =
                make_uint4(q[0], q[1], q[2], q[3]);
        }
        __syncthreads();

        // -------- GEMM1: [64 x 128] x [128 x 48(half)] --------
        float acc[6][4];
        #pragma unroll
        for (int nt = 0; nt < 6; nt++)
            #pragma unroll
            for (int q = 0; q < 4; q++) acc[nt][q] = 0.f;

        #pragma unroll
        for (int ks = 0; ks < 8; ks++) {
            const int kg = 2 * ks;
            uint32_t a[4];
            ldsm_x4(a, aA_row + 16u * ((kg + akg) ^ sw));
            #pragma unroll
            for (int pr = 0; pr < 3; pr++) {
                uint32_t b[4];
                ldsm_x4(b, bB_row + pr * (16u * 256u) + 16u * ((kg + bkg) ^ sw));
                mma_bf16(acc[2 * pr],     a, b[0], b[1]);
                mma_bf16(acc[2 * pr + 1], a, b[2], b[3]);
            }
        }
        __syncthreads();   // all warps done reading A1 before A2 overwrite

        // -------- epilogue 1: bias + relu -> A2 bf16 [p][f] --------
        #pragma unroll
        for (int nt = 0; nt < 6; nt++) {
            const int fg = par * 6 + nt;                 // f-granule
            float h00 = fmaxf(acc[nt][0] + bx[nt], 0.f);
            float h01 = fmaxf(acc[nt][1] + by[nt], 0.f);
            float h10 = fmaxf(acc[nt][2] + bx[nt], 0.f);
            float h11 = fmaxf(acc[nt][3] + by[nt], 0.f);
            *(uint32_t*)(smem + SOFF_A1 + (m0 + g) * 256 + 16 * (fg ^ g) + 4 * t)
                = pack_bf16x2(h00, h01);
            *(uint32_t*)(smem + SOFF_A1 + (m0 + g + 8) * 256 + 16 * (fg ^ g) + 4 * t)
                = pack_bf16x2(h10, h11);
        }
        __syncthreads();

        // -------- GEMM2: [64 x 96] x [96 x 8(half)] --------
        float acc2[4] = {0.f, 0.f, 0.f, 0.f};
        #pragma unroll
        for (int ks = 0; ks < 6; ks++) {
            const int kg = 2 * ks;
            uint32_t a[4];
            ldsm_x4(a, aA_row + 16u * ((kg + akg) ^ sw));
            uint32_t b[2];
            ldsm_x2(b, bB2_row + 16u * ((kg + b2kg) ^ sw));
            mma_bf16(acc2, a, b[0], b[1]);
        }

        // -------- D2 fragments --------
        {
            const int c0 = par * 8 + 2 * t;
            D2s[(m0 + g    ) * 17 + c0    ] = acc2[0];
            D2s[(m0 + g    ) * 17 + c0 + 1] = acc2[1];
            D2s[(m0 + g + 8) * 17 + c0    ] = acc2[2];
            D2s[(m0 + g + 8) * 17 + c0 + 1] = acc2[3];
        }
        __syncthreads();

        // -------- masked residual + coalesced store (3 ch/thread) ----
        {
            const size_t pix = (size_t)n * CHW + (size_t)h * WW + (size_t)(w0 + p);
            #pragma unroll
            for (int cc = 0; cc < 3; cc++) {
                const int c = 3 * qh + cc;
                int m = mask[pix + (size_t)c * HW];
                float u = D2s[p * 17 + c];
                out[pix + (size_t)c * HW] = xcen[cc] + (m ? u : 0.f);
            }
        }
        __syncthreads();   // D2/A2 reads done before next iteration's writes
    }
}

// ---------------- launch ----------------
extern "C" void kernel_launch(void* const* d_in, const int* in_sizes, int n_in,
                              void* d_out, int out_size)
{
    const float* x    = (const float*)d_in[0];
    const float* pw   = (const float*)d_in[1];
    const float* pb   = (const float*)d_in[2];
    const float* w1   = (const float*)d_in[3];
    const float* b1   = (const float*)d_in[4];
    const float* w2   = (const float*)d_in[5];
    const int*   mask = (const int*)  d_in[6];
    float* out = (float*)d_out;

    static bool attr_set = false;
    if (!attr_set) {
        cudaFuncSetAttribute(ca_mma_kernel,
                             cudaFuncAttributeMaxDynamicSharedMemorySize,
                             SMEM_TOTAL);
        attr_set = true;
    }

    ca_setup_kernel<<<N1, 128>>>(pw, pb, w1, b1);

    dim3 grid(1, HH, 8);          // 4096 CTAs, 8 tiles (64px) each
    ca_mma_kernel<<<grid, 256, SMEM_TOTAL>>>(x, w2, mask, out);
}

// round 7
// speedup vs baseline: 5.1778x; 1.0042x over previous
#include <cuda_runtime.h>
#include <cuda_bf16.h>
#include <cstdint>

// ---------------- problem constants ----------------
#define NS   12
#define PC   48
#define HID  96
#define HH   512
#define WW   512
#define HW   (HH*WW)
#define CHW  (NS*HW)

#define MT    64          // pixels per tile
#define K1    128         // 4 groups x 32 slots (27 real taps each)
#define N1    96
#define K2    96
#define N2    16

// smem layout (bytes). Rows are 256B (16 granules of 16B); granule XOR (row&7).
#define SOFF_A1   0                         // A1/A2: 64 rows x 256B
#define SZ_A1     (64 * 256)                // 16384
#define SOFF_B1   (SOFF_A1 + SZ_A1)         // B1: 96 rows x 256B
#define SZ_B1     (96 * 256)                // 24576
#define SOFF_B2   (SOFF_B1 + SZ_B1)         // B2: 16 rows x 256B
#define SZ_B2     (16 * 256)                // 4096
#define SOFF_D2   (SOFF_B2 + SZ_B2)         // D2: 64 x 17 f32
#define SZ_D2     (64 * 17 * 4)             // 4352
#define SOFF_BIAS (SOFF_D2 + SZ_D2)
#define SZ_BIAS   (N1 * 4)
#define SMEM_TOTAL (SOFF_BIAS + SZ_BIAS)    // 49792 B -> 3 CTAs/SM

// ---------------- fused weights (device scratch) ----------------
__device__ __nv_bfloat16 g_B1c[N1 * K1];  // (w1 @ pw) bf16, k = 32*(ci/3)+(ci%3)*9+tap
__device__ float g_b1c[N1];               // w1 @ pb + b1

// ---------------- asm helpers ----------------
__device__ __forceinline__ uint32_t smem_u32(const void* p) {
    uint32_t a;
    asm("{ .reg .u64 t; cvta.to.shared.u64 t, %1; cvt.u32.u64 %0, t; }" : "=r"(a) : "l"(p));
    return a;
}
__device__ __forceinline__ uint32_t pack_bf16x2(float lo, float hi) {
    uint32_t r;
    asm("cvt.rn.bf16x2.f32 %0, %1, %2;" : "=r"(r) : "f"(hi), "f"(lo));
    return r;
}
__device__ __forceinline__ void ldsm_x4(uint32_t r[4], uint32_t addr) {
    asm volatile("ldmatrix.sync.aligned.m8n8.x4.shared.b16 {%0,%1,%2,%3}, [%4];"
                 : "=r"(r[0]), "=r"(r[1]), "=r"(r[2]), "=r"(r[3]) : "r"(addr));
}
__device__ __forceinline__ void ldsm_x2(uint32_t r[2], uint32_t addr) {
    asm volatile("ldmatrix.sync.aligned.m8n8.x2.shared.b16 {%0,%1}, [%2];"
                 : "=r"(r[0]), "=r"(r[1]) : "r"(addr));
}
__device__ __forceinline__ void mma_bf16(float d[4], const uint32_t a[4],
                                         uint32_t b0, uint32_t b1) {
    asm volatile(
        "mma.sync.aligned.m16n8k16.row.col.f32.bf16.bf16.f32 "
        "{%0,%1,%2,%3}, {%4,%5,%6,%7}, {%8,%9}, {%0,%1,%2,%3};"
        : "+f"(d[0]), "+f"(d[1]), "+f"(d[2]), "+f"(d[3])
        : "r"(a[0]), "r"(a[1]), "r"(a[2]), "r"(a[3]), "r"(b0), "r"(b1));
}

// ---------------- setup: fuse conv weights into MLP1 (bf16) ----------------
__global__ void ca_setup_kernel(const float* __restrict__ pw, const float* __restrict__ pb,
                                const float* __restrict__ w1, const float* __restrict__ b1)
{
    int f = blockIdx.x;        // 0..95
    int k = threadIdx.x;       // 0..127
    int grp = k >> 5, slot = k & 31;
    float acc = 0.f;
    if (slot < 27) {
        int ci = 3 * grp + slot / 9;
        int tap = slot % 9;
        #pragma unroll
        for (int c = 0; c < PC; c++)
            acc = fmaf(w1[f * PC + c], pw[(c * NS + ci) * 9 + tap], acc);
    }
    g_B1c[f * K1 + k] = __float2bfloat16(acc);
    if (k == 0) {
        float b = b1[f];
        for (int c = 0; c < PC; c++) b = fmaf(w1[f * PC + c], pb[c], b);
        g_b1c[f] = b;
    }
}

// ---------------- main kernel ----------------
__global__ __launch_bounds__(256, 3)
void ca_mma_kernel(const float* __restrict__ x,
                   const float* __restrict__ w2,
                   const int*   __restrict__ mask,
                   float* __restrict__ out)
{
    extern __shared__ __align__(256) char smem[];
    const uint32_t su  = smem_u32(smem);
    const uint32_t sbA = su + SOFF_A1;
    const uint32_t sbB1= su + SOFF_B1;
    const uint32_t sbB2= su + SOFF_B2;
    float* D2s   = (float*)(smem + SOFF_D2);    // [64][17]
    float* biass = (float*)(smem + SOFF_BIAS);  // [96]

    const int tid  = threadIdx.x;
    const int wid  = tid >> 5;
    const int lane = tid & 31;
    const int sw   = lane & 7;
    const int par  = wid & 1;              // n-half: [48*par, 48*par+48)
    const int m0   = (wid >> 1) * 16;
    const int n    = blockIdx.z;
    const int h    = blockIdx.y;

    // -------- stage constant weights (once per CTA) --------
    {   // B1: [f][k] bf16, granule-copy with XOR swizzle
        const uint16_t* src = (const uint16_t*)g_B1c;
        for (int i = tid; i < N1 * 16; i += 256) {
            int f = i >> 4, gj = i & 15;
            uint4 q = *(const uint4*)(src + f * K1 + gj * 8);
            *(uint4*)(smem + SOFF_B1 + f * 256 + 16 * (gj ^ (f & 7))) = q;
        }
    }
    for (int i = tid; i < N2 * K2; i += 256) { // B2: w2[o][f] -> [n=o][k=f]
        int o = i / K2, k = i - o * K2;
        __nv_bfloat16 v = (o < NS) ? __float2bfloat16(w2[o * HID + k])
                                   : __float2bfloat16(0.f);
        *(__nv_bfloat16*)(smem + SOFF_B2 + o * 256 + 16 * ((k >> 3) ^ (o & 7)) + 2 * (k & 7)) = v;
    }
    if (tid < N1) biass[tid] = g_b1c[tid];
    __syncthreads();

    // bias regs for this warp's 6 n-tiles
    const int t = lane & 3, g = lane >> 2;
    float bx[6], by[6];
    #pragma unroll
    for (int nt = 0; nt < 6; nt++) {
        bx[nt] = biass[par * 48 + nt * 8 + 2 * t];
        by[nt] = biass[par * 48 + nt * 8 + 2 * t + 1];
    }

    // ldmatrix per-lane address components
    const uint32_t aA_row = sbA + (uint32_t)(m0 + 8 * ((lane >> 3) & 1) + sw) * 256;
    const int akg = lane >> 4;                   // 0/1 : k-granule offset
    const uint32_t bB_row = sbB1 + (uint32_t)(par * 48 + 8 * (lane >> 4) + sw) * 256;
    const int bkg = (lane >> 3) & 1;
    const uint32_t bB2_row = sbB2 + (uint32_t)(par * 8 + sw) * 256;
    const int b2kg = (lane >> 3) & 1;            // lanes 16-31 mirror 0-15

    const float* xn = x + (size_t)n * CHW;
    const int p  = tid & 63;               // pixel within tile
    const int qh = tid >> 6;               // channel group 0..3 (3 ch each)

    for (int it = 0; it < 8; it++) {
        const int w0  = it << 6;
        const int gwm = (w0 + p + WW - 1) & (WW - 1);
        const int gw0 = w0 + p;
        const int gwp = (w0 + p + 1) & (WW - 1);

        // -------- stage im2col A1: 27 taps -> 4 x STS.128, XOR swizzle ----
        float vals[27];
        #pragma unroll
        for (int cc = 0; cc < 3; cc++) {
            const int ci = 3 * qh + cc;
            #pragma unroll
            for (int dh = 0; dh < 3; dh++) {
                const int gh = (h + dh - 1) & (HH - 1);
                const float* rp = xn + (size_t)ci * HW + (size_t)gh * WW;
                vals[cc * 9 + dh * 3 + 0] = __ldg(rp + gwm);
                vals[cc * 9 + dh * 3 + 1] = __ldg(rp + gw0);
                vals[cc * 9 + dh * 3 + 2] = __ldg(rp + gwp);
            }
        }
        float xcen[3] = { vals[4], vals[13], vals[22] };
        #pragma unroll
        for (int j = 0; j < 4; j++) {
            uint32_t q[4];
            #pragma unroll
            for (int wq = 0; wq < 4; wq++) {
                const int s0 = 8 * j + 2 * wq;
                float lo = (s0     < 27) ? vals[s0]     : 0.f;
                float hi = (s0 + 1 < 27) ? vals[s0 + 1] : 0.f;
                q[wq] = pack_bf16x2(lo, hi);
            }
            const int gran = (4 * qh + j) ^ (p & 7);
            *(uint4*)(smem + SOFF_A1 + p * 256 + gran * 16) =
                make_uint4(q[0], q[1], q[2], q[3]);
        }
        __syncthreads();

        // -------- GEMM1: [64 x 128] x [128 x 48(half)] --------
        float acc[6][4];
        #pragma unroll
        for (int nt = 0; nt < 6; nt++)
            #pragma unroll
            for (int q = 0; q < 4; q++) acc[nt][q] = 0.f;

        #pragma unroll
        for (int ks = 0; ks < 8; ks++) {
            const int kg = 2 * ks;
            uint32_t a[4];
            ldsm_x4(a, aA_row + 16u * ((kg + akg) ^ sw));
            #pragma unroll
            for (int pr = 0; pr < 3; pr++) {
                uint32_t b[4];
                ldsm_x4(b, bB_row + pr * (16u * 256u) + 16u * ((kg + bkg) ^ sw));
                mma_bf16(acc[2 * pr],     a, b[0], b[1]);
                mma_bf16(acc[2 * pr + 1], a, b[2], b[3]);
            }
        }
        __syncthreads();   // all warps done reading A1 before A2 overwrite

        // -------- epilogue 1: bias + relu -> A2 bf16 [p][f] --------
        #pragma unroll
        for (int nt = 0; nt < 6; nt++) {
            const int fg = par * 6 + nt;                 // f-granule
            float h00 = fmaxf(acc[nt][0] + bx[nt], 0.f);
            float h01 = fmaxf(acc[nt][1] + by[nt], 0.f);
            float h10 = fmaxf(acc[nt][2] + bx[nt], 0.f);
            float h11 = fmaxf(acc[nt][3] + by[nt], 0.f);
            *(uint32_t*)(smem + SOFF_A1 + (m0 + g) * 256 + 16 * (fg ^ g) + 4 * t)
                = pack_bf16x2(h00, h01);
            *(uint32_t*)(smem + SOFF_A1 + (m0 + g + 8) * 256 + 16 * (fg ^ g) + 4 * t)
                = pack_bf16x2(h10, h11);
        }
        __syncthreads();

        // -------- GEMM2: [64 x 96] x [96 x 8(half)] --------
        float acc2[4] = {0.f, 0.f, 0.f, 0.f};
        #pragma unroll
        for (int ks = 0; ks < 6; ks++) {
            const int kg = 2 * ks;
            uint32_t a[4];
            ldsm_x4(a, aA_row + 16u * ((kg + akg) ^ sw));
            uint32_t b[2];
            ldsm_x2(b, bB2_row + 16u * ((kg + b2kg) ^ sw));
            mma_bf16(acc2, a, b[0], b[1]);
        }

        // -------- D2 fragments --------
        {
            const int c0 = par * 8 + 2 * t;
            D2s[(m0 + g    ) * 17 + c0    ] = acc2[0];
            D2s[(m0 + g    ) * 17 + c0 + 1] = acc2[1];
            D2s[(m0 + g + 8) * 17 + c0    ] = acc2[2];
            D2s[(m0 + g + 8) * 17 + c0 + 1] = acc2[3];
        }
        __syncthreads();

        // -------- masked residual + coalesced store (3 ch/thread) ----
        {
            const size_t pix = (size_t)n * CHW + (size_t)h * WW + (size_t)(w0 + p);
            #pragma unroll
            for (int cc = 0; cc < 3; cc++) {
                const int c = 3 * qh + cc;
                int m = mask[pix + (size_t)c * HW];
                float u = D2s[p * 17 + c];
                out[pix + (size_t)c * HW] = xcen[cc] + (m ? u : 0.f);
            }
        }
        __syncthreads();   // D2/A2 reads done before next iteration's writes
    }
}

// ---------------- launch ----------------
extern "C" void kernel_launch(void* const* d_in, const int* in_sizes, int n_in,
                              void* d_out, int out_size)
{
    const float* x    = (const float*)d_in[0];
    const float* pw   = (const float*)d_in[1];
    const float* pb   = (const float*)d_in[2];
    const float* w1   = (const float*)d_in[3];
    const float* b1   = (const float*)d_in[4];
    const float* w2   = (const float*)d_in[5];
    const int*   mask = (const int*)  d_in[6];
    float* out = (float*)d_out;

    static bool attr_set = false;
    if (!attr_set) {
        cudaFuncSetAttribute(ca_mma_kernel,
                             cudaFuncAttributeMaxDynamicSharedMemorySize,
                             SMEM_TOTAL);
        attr_set = true;
    }

    ca_setup_kernel<<<N1, 128>>>(pw, pb, w1, b1);

    dim3 grid(1, HH, 8);          // 4096 CTAs, 8 tiles (64px) each
    ca_mma_kernel<<<grid, 256, SMEM_TOTAL>>>(x, w2, mask, out);
}